// round 11
// baseline (speedup 1.0000x reference)
#include <cuda_runtime.h>
#include <cuda_bf16.h>
#include <cstdint>

#define L 4096
#define DE 1024
#define DV 1024
#define HEXP 0.2f
#define DTF (1.0f / 4096.0f)
#define EPSV 1e-8f
#define FFT_N 8192

// ---------------- device scratch (static, no runtime alloc) ----------------
__device__ __nv_bfloat16 g_Et_hi[L * DE];
__device__ __nv_bfloat16 g_Et_lo[L * DE];
__device__ __nv_bfloat16 g_W_hi[DV * DE];
__device__ __nv_bfloat16 g_W_lo[DV * DE];
__device__ float g_Yt[(size_t)DV * L];      // Y^T fp32 ([v][l], l contiguous)
__device__ float2 g_tw[FFT_N];              // exp(-2*pi*i*n/N)
__device__ float2 g_F[FFT_N];               // FFT(f_padded)/N

// ---------------- helpers ---------------------------------------------------
__device__ __forceinline__ uint32_t smem_u32(const void* p) {
    uint32_t a;
    asm("{ .reg .u64 t; cvta.to.shared.u64 t, %1; cvt.u32.u64 %0, t; }" : "=r"(a) : "l"(p));
    return a;
}
#define SW64(o) ((uint32_t)(o) ^ ((((uint32_t)(o)) >> 3) & 0x30u))

__device__ __forceinline__ void cpasync16(uint32_t dst, const void* src) {
    asm volatile("cp.async.cg.shared.global [%0], [%1], 16;" :: "r"(dst), "l"(src));
}
#define CP_COMMIT() asm volatile("cp.async.commit_group;" ::: "memory")
#define CP_WAIT2()  asm volatile("cp.async.wait_group 2;" ::: "memory")

__device__ __forceinline__ void ldsm4(uint32_t* r, uint32_t addr) {
    asm volatile("ldmatrix.sync.aligned.m8n8.x4.shared.b16 {%0,%1,%2,%3}, [%4];"
                 : "=r"(r[0]), "=r"(r[1]), "=r"(r[2]), "=r"(r[3]) : "r"(addr));
}
__device__ __forceinline__ void mma_bf16(float* c, const uint32_t* a, const uint32_t* b) {
    asm volatile(
        "mma.sync.aligned.m16n8k16.row.col.f32.bf16.bf16.f32 "
        "{%0,%1,%2,%3}, {%4,%5,%6,%7}, {%8,%9}, {%0,%1,%2,%3};"
        : "+f"(c[0]), "+f"(c[1]), "+f"(c[2]), "+f"(c[3])
        : "r"(a[0]), "r"(a[1]), "r"(a[2]), "r"(a[3]), "r"(b[0]), "r"(b[1]));
}

__device__ __forceinline__ float2 cmul(float2 a, float2 b) {
    return make_float2(a.x * b.x - a.y * b.y, a.x * b.y + a.y * b.x);
}
__device__ __forceinline__ float2 cadd(float2 a, float2 b) { return make_float2(a.x + b.x, a.y + b.y); }
__device__ __forceinline__ float2 csub(float2 a, float2 b) { return make_float2(a.x - b.x, a.y - b.y); }

// ---------------- GEMM tiling: CTA 128x128, 4 warps (64x64 each), BK=32 -----
#define STAGE_BYTES 32768
#define T_AHI 0
#define T_ALO 8192
#define T_BHI 16384
#define T_BLO 24576
#define GEMM_SMEM (3 * STAGE_BYTES)

__device__ __forceinline__ void fill_tile32(uint32_t dstbase,
                                            const __nv_bfloat16* __restrict__ g,
                                            int row0, int k0, int stride, int tid) {
#pragma unroll
    for (int i = 0; i < 4; ++i) {
        int q = tid + i * 128;
        int r = q >> 2, c = q & 3;
        uint32_t o = (uint32_t)(r * 64 + c * 16);
        cpasync16(dstbase + SW64(o), g + (size_t)(row0 + r) * stride + k0 + c * 8);
    }
}

// ---------------- pre-kernels -----------------------------------------------
__global__ void transpose_E_kernel(const float* __restrict__ E) {
    __shared__ float t[64][33];
    int bx = blockIdx.x, by = blockIdx.y;
    int tx = threadIdx.x, ty = threadIdx.y;        // block (32, 8)
#pragma unroll
    for (int i = 0; i < 8; ++i)
        t[ty + 8 * i][tx] = E[(size_t)(by * 64 + ty + 8 * i) * L + bx * 32 + tx];
    __syncthreads();
#pragma unroll
    for (int i = 0; i < 4; ++i) {
        int ll = ty + 8 * i;
        float v0 = t[2 * tx][ll];
        float v1 = t[2 * tx + 1][ll];
        __nv_bfloat16 h0 = __float2bfloat16(v0);
        __nv_bfloat16 h1 = __float2bfloat16(v1);
        __nv_bfloat162 hp; hp.x = h0; hp.y = h1;
        __nv_bfloat162 lp;
        lp.x = __float2bfloat16(v0 - __bfloat162float(h0));
        lp.y = __float2bfloat16(v1 - __bfloat162float(h1));
        size_t o = (size_t)(bx * 32 + ll) * DE + by * 64 + 2 * tx;
        *reinterpret_cast<__nv_bfloat162*>(&g_Et_hi[o]) = hp;
        *reinterpret_cast<__nv_bfloat162*>(&g_Et_lo[o]) = lp;
    }
}

// float4 loads, 8 elems/thread, uint2-packed stores
__global__ void convert_W_kernel(const float* __restrict__ W) {
    int base = (blockIdx.x * 256 + threadIdx.x) * 8;
#pragma unroll
    for (int h = 0; h < 2; ++h) {
        float4 v = *reinterpret_cast<const float4*>(&W[base + 4 * h]);
        float vv[4] = {v.x, v.y, v.z, v.w};
        uint32_t hu[2], lu[2];
#pragma unroll
        for (int p = 0; p < 2; ++p) {
            __nv_bfloat16 h0 = __float2bfloat16(vv[2 * p]);
            __nv_bfloat16 h1 = __float2bfloat16(vv[2 * p + 1]);
            __nv_bfloat162 hp; hp.x = h0; hp.y = h1;
            __nv_bfloat162 lp;
            lp.x = __float2bfloat16(vv[2 * p] - __bfloat162float(h0));
            lp.y = __float2bfloat16(vv[2 * p + 1] - __bfloat162float(h1));
            hu[p] = *reinterpret_cast<uint32_t*>(&hp);
            lu[p] = *reinterpret_cast<uint32_t*>(&lp);
        }
        *reinterpret_cast<uint2*>(&g_W_hi[base + 4 * h]) = make_uint2(hu[0], hu[1]);
        *reinterpret_cast<uint2*>(&g_W_lo[base + 4 * h]) = make_uint2(lu[0], lu[1]);
    }
}

// ---------------- radix-8 FFT machinery, skewed smem -------------------------
#define PHY(i) ((i) + ((i) >> 4))
#define FFT_BUF 8704
#define C_SQ2 0.70710678118654752f

// Full DFT8 combine from t/s inputs; writes 8 outputs with twiddles.
template <int INV>
__device__ __forceinline__ void dft8_store(float2* dst, int u, int k, int m,
                                           float2 t0, float2 t1, float2 t2, float2 t3,
                                           float2 s0, float2 s1, float2 s2, float2 s3) {
    float2 mjt3 = INV ? make_float2(-t3.y, t3.x) : make_float2(t3.y, -t3.x);
    float2 mjs3 = INV ? make_float2(-s3.y, s3.x) : make_float2(s3.y, -s3.x);
    float2 E0 = cadd(t0, t2), E2 = csub(t0, t2);
    float2 E1 = cadd(t1, mjt3), E3 = csub(t1, mjt3);
    float2 O0 = cadd(s0, s2), O2 = csub(s0, s2);
    float2 O1 = cadd(s1, mjs3), O3 = csub(s1, mjs3);
    float2 w1O1 = INV ? make_float2(C_SQ2 * (O1.x - O1.y), C_SQ2 * (O1.x + O1.y))
                      : make_float2(C_SQ2 * (O1.x + O1.y), C_SQ2 * (O1.y - O1.x));
    float2 w2O2 = INV ? make_float2(-O2.y, O2.x) : make_float2(O2.y, -O2.x);
    float2 w3O3 = INV ? make_float2(-C_SQ2 * (O3.x + O3.y), C_SQ2 * (O3.x - O3.y))
                      : make_float2(C_SQ2 * (O3.y - O3.x), -C_SQ2 * (O3.x + O3.y));
    float2 X[8];
    X[0] = cadd(E0, O0);   X[4] = csub(E0, O0);
    X[1] = cadd(E1, w1O1); X[5] = csub(E1, w1O1);
    X[2] = cadd(E2, w2O2); X[6] = csub(E2, w2O2);
    X[3] = cadd(E3, w3O3); X[7] = csub(E3, w3O3);
    int b8 = 8 * u + k;
    dst[PHY(b8)] = X[0];
#pragma unroll
    for (int j = 1; j < 8; ++j) {
        float2 w = g_tw[j * u];
        if (INV) w.y = -w.y;
        dst[PHY(b8 + j * m)] = cmul(w, X[j]);
    }
}

// generic radix-8 stage over smem
template <int NT, int INV>
__device__ __forceinline__ void r8_stage(const float2* src, float2* dst, int tid, int m) {
#pragma unroll
    for (int it = 0; it < 1024 / NT; ++it) {
        int bf = tid + it * NT;
        int k = bf & (m - 1);
        int u = bf - k;
        float2 x0 = src[PHY(bf)];
        float2 x1 = src[PHY(bf + 1024)];
        float2 x2 = src[PHY(bf + 2048)];
        float2 x3 = src[PHY(bf + 3072)];
        float2 x4 = src[PHY(bf + 4096)];
        float2 x5 = src[PHY(bf + 5120)];
        float2 x6 = src[PHY(bf + 6144)];
        float2 x7 = src[PHY(bf + 7168)];
        dft8_store<INV>(dst, u, k, m,
                        cadd(x0, x4), csub(x0, x4), cadd(x2, x6), csub(x2, x6),
                        cadd(x1, x5), csub(x1, x5), cadd(x3, x7), csub(x3, x7));
    }
    __syncthreads();
}

// fft_F: single CTA; computes g_tw itself, then FFT of f, then writes g_F.
__global__ __launch_bounds__(256) void fft_F_kernel() {
    extern __shared__ float2 sm[];
    float2* A = sm;
    float2* B = sm + FFT_BUF;
    int tid = threadIdx.x;
    // twiddle table (also used later by conv)
#pragma unroll
    for (int it = 0; it < 32; ++it) {
        int n = tid + it * 256;
        float s, c;
        sincospif(-2.0f * (float)n / (float)FFT_N, &s, &c);
        g_tw[n] = make_float2(c, s);
    }
    // input
#pragma unroll
    for (int it = 0; it < 32; ++it) {
        int d = tid + it * 256;
        float v = 0.f;
        if (d < L) {
            float base = (d == 0) ? EPSV : ((float)d * DTF + EPSV);
            v = powf(base, HEXP);
        }
        A[PHY(d)] = make_float2(v, 0.f);
    }
    __syncthreads();
    // 4 r8 stages + final r2
    {
        float2* src = A;
        float2* dst = B;
        int m = 1;
#pragma unroll 1
        for (int s = 0; s < 4; ++s) {
            r8_stage<256, 0>(src, dst, tid, m);
            float2* t = src; src = dst; dst = t;
            m <<= 3;
        }
        const float scale = 1.0f / (float)FFT_N;
#pragma unroll
        for (int it = 0; it < 16; ++it) {
            int k = tid + it * 256;
            float2 a = src[PHY(k)];
            float2 b = src[PHY(k + FFT_N / 2)];
            float2 lo = cadd(a, b);
            float2 hi = csub(a, b);
            g_F[k] = make_float2(lo.x * scale, lo.y * scale);
            g_F[k + FFT_N / 2] = make_float2(hi.x * scale, hi.y * scale);
        }
    }
}

// ---------------- conv: fused, zero-pad-aware, half-output, direct store -----
#define CONV_NT 512
__global__ __launch_bounds__(CONV_NT) void conv_kernel(float* __restrict__ out) {
    extern __shared__ float2 sm[];
    float2* A = sm;
    float2* B = sm + FFT_BUF;
    int tid = threadIdx.x;
    int c2 = blockIdx.x * 2;
    const float* __restrict__ ya = g_Yt + (size_t)c2 * L;
    const float* __restrict__ yb = g_Yt + (size_t)(c2 + 1) * L;

    // ---- forward stage 0 (m=1) straight from global; x4..x7 = 0 ----
#pragma unroll
    for (int it = 0; it < 1024 / CONV_NT; ++it) {
        int bf = tid + it * CONV_NT;
        float2 x0 = make_float2(ya[bf], yb[bf]);
        float2 x1 = make_float2(ya[bf + 1024], yb[bf + 1024]);
        float2 x2 = make_float2(ya[bf + 2048], yb[bf + 2048]);
        float2 x3 = make_float2(ya[bf + 3072], yb[bf + 3072]);
        // x4..7 = 0  =>  t0=t1=x0, t2=t3=x2, s0=s1=x1, s2=s3=x3
        dft8_store<0>(A, bf, 0, 1, x0, x0, x2, x2, x1, x1, x3, x3);
    }
    __syncthreads();
    // ---- forward stages 1..3 ----
    r8_stage<CONV_NT, 0>(A, B, tid, 8);
    r8_stage<CONV_NT, 0>(B, A, tid, 64);
    r8_stage<CONV_NT, 0>(A, B, tid, 512);
    // ---- forward final r2 fused with F multiply -> A ----
#pragma unroll
    for (int it = 0; it < 4096 / CONV_NT; ++it) {
        int k = tid + it * CONV_NT;
        float2 a = B[PHY(k)];
        float2 b = B[PHY(k + FFT_N / 2)];
        A[PHY(k)] = cmul(cadd(a, b), g_F[k]);
        A[PHY(k + FFT_N / 2)] = cmul(csub(a, b), g_F[k + FFT_N / 2]);
    }
    __syncthreads();
    // ---- inverse stages 0..3 ----
    r8_stage<CONV_NT, 1>(A, B, tid, 1);
    r8_stage<CONV_NT, 1>(B, A, tid, 8);
    r8_stage<CONV_NT, 1>(A, B, tid, 64);
    r8_stage<CONV_NT, 1>(B, A, tid, 512);
    // ---- inverse final r2: outputs k < 4096 written DIRECTLY to out[k][c2..c2+1]
    // (adjacent channels -> contiguous float2; L2 merges sectors across CTAs)
#pragma unroll
    for (int it = 0; it < 4096 / CONV_NT; ++it) {
        int k = tid + it * CONV_NT;
        float2 a = A[PHY(k)];
        float2 b = A[PHY(k + FFT_N / 2)];
        float2 s = cadd(a, b);
        *reinterpret_cast<float2*>(&out[(size_t)k * DV + c2]) = s;
    }
}

// ---------------- GEMM1 compute core: warp tile 64x64 -----------------------
__device__ __forceinline__ void compute_stage64(uint32_t sbase, int lane, int wm, int wn,
                                                float acc[4][8][4]) {
    const int arow = lane & 15;
    const int acolb = (lane >> 4) << 4;
    const int brow = (lane & 7) + ((lane >> 4) << 3);
    const int bcolb = ((lane >> 3) & 1) << 4;
#pragma unroll
    for (int kk = 0; kk < 2; ++kk) {
        uint32_t aH[4][4], aL[4][4];
#pragma unroll
        for (int mi = 0; mi < 4; ++mi) {
            uint32_t o = SW64((uint32_t)((wm * 64 + mi * 16 + arow) * 64 + acolb)) ^ (kk << 5);
            ldsm4(aH[mi], sbase + T_AHI + o);
            ldsm4(aL[mi], sbase + T_ALO + o);
        }
#pragma unroll
        for (int pi = 0; pi < 4; ++pi) {
            uint32_t bH[4], bL[4];
            uint32_t o = SW64((uint32_t)((wn * 64 + pi * 16 + brow) * 64 + bcolb)) ^ (kk << 5);
            ldsm4(bH, sbase + T_BHI + o);
            ldsm4(bL, sbase + T_BLO + o);
#pragma unroll
            for (int mi = 0; mi < 4; ++mi)
#pragma unroll
                for (int q = 0; q < 2; ++q) {
                    mma_bf16(acc[mi][pi * 2 + q], aH[mi], &bH[q * 2]);
                    mma_bf16(acc[mi][pi * 2 + q], aH[mi], &bL[q * 2]);
                    mma_bf16(acc[mi][pi * 2 + q], aL[mi], &bH[q * 2]);
                }
        }
    }
}

__global__ __launch_bounds__(128, 2) void gemm1_mma() {
    extern __shared__ char smem[];
    const uint32_t sb = smem_u32(smem);
    const int tid = threadIdx.x, lane = tid & 31, wid = tid >> 5;
    const int wm = wid & 1, wn = (wid >> 1) & 1;
    const int l0 = blockIdx.x * 128;
    const int v0 = blockIdx.y * 128;
    const int KT = DE / 32;

    float acc[4][8][4];
#pragma unroll
    for (int mi = 0; mi < 4; ++mi)
#pragma unroll
        for (int ni = 0; ni < 8; ++ni)
#pragma unroll
            for (int r = 0; r < 4; ++r) acc[mi][ni][r] = 0.f;

#pragma unroll
    for (int s = 0; s < 2; ++s) {
        uint32_t st = sb + s * STAGE_BYTES;
        int k0 = s * 32;
        fill_tile32(st + T_AHI, g_W_hi, v0, k0, DE, tid);
        fill_tile32(st + T_ALO, g_W_lo, v0, k0, DE, tid);
        fill_tile32(st + T_BHI, g_Et_hi, l0, k0, DE, tid);
        fill_tile32(st + T_BLO, g_Et_lo, l0, k0, DE, tid);
        CP_COMMIT();
    }
    for (int kt = 0; kt < KT; ++kt) {
        int ls = kt + 2;
        if (ls < KT) {
            uint32_t st = sb + (ls % 3) * STAGE_BYTES;
            int k0 = ls * 32;
            fill_tile32(st + T_AHI, g_W_hi, v0, k0, DE, tid);
            fill_tile32(st + T_ALO, g_W_lo, v0, k0, DE, tid);
            fill_tile32(st + T_BHI, g_Et_hi, l0, k0, DE, tid);
            fill_tile32(st + T_BLO, g_Et_lo, l0, k0, DE, tid);
        }
        CP_COMMIT();
        CP_WAIT2();
        __syncthreads();
        compute_stage64(sb + (kt % 3) * STAGE_BYTES, lane, wm, wn, acc);
        __syncthreads();
    }

#pragma unroll
    for (int mi = 0; mi < 4; ++mi)
#pragma unroll
        for (int ni = 0; ni < 8; ++ni) {
            const float* c = acc[mi][ni];
            int v_ = v0 + wm * 64 + mi * 16 + (lane >> 2);
            int l_ = l0 + wn * 64 + ni * 8 + 2 * (lane & 3);
#pragma unroll
            for (int h = 0; h < 2; ++h) {
                float2 p;
                p.x = c[2 * h];
                p.y = c[2 * h + 1];
                *reinterpret_cast<float2*>(&g_Yt[(size_t)(v_ + 8 * h) * L + l_]) = p;
            }
        }
}

// ---------------------------------------------------------------------------
#define FFT_SMEM (2 * FFT_BUF * (int)sizeof(float2))

extern "C" void kernel_launch(void* const* d_in, const int* in_sizes, int n_in,
                              void* d_out, int out_size) {
    const float* E = (const float*)d_in[0];   // (1024, 4096)
    const float* W = (const float*)d_in[1];   // (1024, 1024)
    float* out = (float*)d_out;               // (4096, 1024)

    cudaFuncSetAttribute(gemm1_mma, cudaFuncAttributeMaxDynamicSharedMemorySize, GEMM_SMEM);
    cudaFuncSetAttribute(fft_F_kernel, cudaFuncAttributeMaxDynamicSharedMemorySize, FFT_SMEM);
    cudaFuncSetAttribute(conv_kernel, cudaFuncAttributeMaxDynamicSharedMemorySize, FFT_SMEM);

    fft_F_kernel<<<1, 256, FFT_SMEM>>>();
    transpose_E_kernel<<<dim3(L / 32, DE / 64), dim3(32, 8)>>>(E);
    convert_W_kernel<<<(DV * DE) / (256 * 8), 256>>>(W);
    gemm1_mma<<<dim3(L / 128, DV / 128), 128, GEMM_SMEM>>>();
    conv_kernel<<<DV / 2, CONV_NT, FFT_SMEM>>>(out);
}

// round 12
// speedup vs baseline: 1.0473x; 1.0473x over previous
#include <cuda_runtime.h>
#include <cuda_bf16.h>
#include <cstdint>

#define L 4096
#define DE 1024
#define DV 1024
#define HEXP 0.2f
#define DTF (1.0f / 4096.0f)
#define EPSV 1e-8f
#define FFT_N 8192

// ---------------- device scratch (static, no runtime alloc) ----------------
__device__ __nv_bfloat16 g_Et_hi[L * DE];
__device__ __nv_bfloat16 g_Et_lo[L * DE];
__device__ __nv_bfloat16 g_W_hi[DV * DE];
__device__ __nv_bfloat16 g_W_lo[DV * DE];
__device__ float g_Yt[(size_t)DV * L];      // Y^T fp32 ([v][l], l contiguous)
__device__ float g_outT[(size_t)DV * L];    // conv result [c][i]
__device__ float2 g_tw[FFT_N];              // exp(-2*pi*i*n/N)
__device__ float2 g_F[FFT_N];               // FFT(f_padded)/N

// ---------------- helpers ---------------------------------------------------
__device__ __forceinline__ uint32_t smem_u32(const void* p) {
    uint32_t a;
    asm("{ .reg .u64 t; cvta.to.shared.u64 t, %1; cvt.u32.u64 %0, t; }" : "=r"(a) : "l"(p));
    return a;
}
#define SW64(o) ((uint32_t)(o) ^ ((((uint32_t)(o)) >> 3) & 0x30u))

__device__ __forceinline__ void cpasync16(uint32_t dst, const void* src) {
    asm volatile("cp.async.cg.shared.global [%0], [%1], 16;" :: "r"(dst), "l"(src));
}
#define CP_COMMIT() asm volatile("cp.async.commit_group;" ::: "memory")
#define CP_WAIT2()  asm volatile("cp.async.wait_group 2;" ::: "memory")

__device__ __forceinline__ void ldsm4(uint32_t* r, uint32_t addr) {
    asm volatile("ldmatrix.sync.aligned.m8n8.x4.shared.b16 {%0,%1,%2,%3}, [%4];"
                 : "=r"(r[0]), "=r"(r[1]), "=r"(r[2]), "=r"(r[3]) : "r"(addr));
}
__device__ __forceinline__ void mma_bf16(float* c, const uint32_t* a, const uint32_t* b) {
    asm volatile(
        "mma.sync.aligned.m16n8k16.row.col.f32.bf16.bf16.f32 "
        "{%0,%1,%2,%3}, {%4,%5,%6,%7}, {%8,%9}, {%0,%1,%2,%3};"
        : "+f"(c[0]), "+f"(c[1]), "+f"(c[2]), "+f"(c[3])
        : "r"(a[0]), "r"(a[1]), "r"(a[2]), "r"(a[3]), "r"(b[0]), "r"(b[1]));
}

__device__ __forceinline__ float2 cmul(float2 a, float2 b) {
    return make_float2(a.x * b.x - a.y * b.y, a.x * b.y + a.y * b.x);
}
__device__ __forceinline__ float2 cadd(float2 a, float2 b) { return make_float2(a.x + b.x, a.y + b.y); }
__device__ __forceinline__ float2 csub(float2 a, float2 b) { return make_float2(a.x - b.x, a.y - b.y); }

// ---------------- GEMM tiling: CTA 128x128, 4 warps (64x64 each), BK=32 -----
#define STAGE_BYTES 32768
#define T_AHI 0
#define T_ALO 8192
#define T_BHI 16384
#define T_BLO 24576
#define GEMM_SMEM (3 * STAGE_BYTES)

__device__ __forceinline__ void fill_tile32(uint32_t dstbase,
                                            const __nv_bfloat16* __restrict__ g,
                                            int row0, int k0, int stride, int tid) {
#pragma unroll
    for (int i = 0; i < 4; ++i) {
        int q = tid + i * 128;
        int r = q >> 2, c = q & 3;
        uint32_t o = (uint32_t)(r * 64 + c * 16);
        cpasync16(dstbase + SW64(o), g + (size_t)(row0 + r) * stride + k0 + c * 8);
    }
}

// ---------------- pre-kernels -----------------------------------------------
__global__ void transpose_E_kernel(const float* __restrict__ E) {
    __shared__ float t[64][33];
    int bx = blockIdx.x, by = blockIdx.y;
    int tx = threadIdx.x, ty = threadIdx.y;        // block (32, 8)
#pragma unroll
    for (int i = 0; i < 8; ++i)
        t[ty + 8 * i][tx] = E[(size_t)(by * 64 + ty + 8 * i) * L + bx * 32 + tx];
    __syncthreads();
#pragma unroll
    for (int i = 0; i < 4; ++i) {
        int ll = ty + 8 * i;
        float v0 = t[2 * tx][ll];
        float v1 = t[2 * tx + 1][ll];
        __nv_bfloat16 h0 = __float2bfloat16(v0);
        __nv_bfloat16 h1 = __float2bfloat16(v1);
        __nv_bfloat162 hp; hp.x = h0; hp.y = h1;
        __nv_bfloat162 lp;
        lp.x = __float2bfloat16(v0 - __bfloat162float(h0));
        lp.y = __float2bfloat16(v1 - __bfloat162float(h1));
        size_t o = (size_t)(bx * 32 + ll) * DE + by * 64 + 2 * tx;
        *reinterpret_cast<__nv_bfloat162*>(&g_Et_hi[o]) = hp;
        *reinterpret_cast<__nv_bfloat162*>(&g_Et_lo[o]) = lp;
    }
}

// float4 loads, 8 elems/thread, uint2-packed stores
__global__ void convert_W_kernel(const float* __restrict__ W) {
    int base = (blockIdx.x * 256 + threadIdx.x) * 8;
#pragma unroll
    for (int h = 0; h < 2; ++h) {
        float4 v = *reinterpret_cast<const float4*>(&W[base + 4 * h]);
        float vv[4] = {v.x, v.y, v.z, v.w};
        uint32_t hu[2], lu[2];
#pragma unroll
        for (int p = 0; p < 2; ++p) {
            __nv_bfloat16 h0 = __float2bfloat16(vv[2 * p]);
            __nv_bfloat16 h1 = __float2bfloat16(vv[2 * p + 1]);
            __nv_bfloat162 hp; hp.x = h0; hp.y = h1;
            __nv_bfloat162 lp;
            lp.x = __float2bfloat16(vv[2 * p] - __bfloat162float(h0));
            lp.y = __float2bfloat16(vv[2 * p + 1] - __bfloat162float(h1));
            hu[p] = *reinterpret_cast<uint32_t*>(&hp);
            lu[p] = *reinterpret_cast<uint32_t*>(&lp);
        }
        *reinterpret_cast<uint2*>(&g_W_hi[base + 4 * h]) = make_uint2(hu[0], hu[1]);
        *reinterpret_cast<uint2*>(&g_W_lo[base + 4 * h]) = make_uint2(lu[0], lu[1]);
    }
}

// ---------------- radix-8 FFT machinery, skewed smem -------------------------
#define PHY(i) ((i) + ((i) >> 4))
#define FFT_BUF 8704
#define C_SQ2 0.70710678118654752f

// Full DFT8 combine from t/s inputs; writes 8 outputs with twiddles.
template <int INV>
__device__ __forceinline__ void dft8_store(float2* dst, int u, int k, int m,
                                           float2 t0, float2 t1, float2 t2, float2 t3,
                                           float2 s0, float2 s1, float2 s2, float2 s3) {
    float2 mjt3 = INV ? make_float2(-t3.y, t3.x) : make_float2(t3.y, -t3.x);
    float2 mjs3 = INV ? make_float2(-s3.y, s3.x) : make_float2(s3.y, -s3.x);
    float2 E0 = cadd(t0, t2), E2 = csub(t0, t2);
    float2 E1 = cadd(t1, mjt3), E3 = csub(t1, mjt3);
    float2 O0 = cadd(s0, s2), O2 = csub(s0, s2);
    float2 O1 = cadd(s1, mjs3), O3 = csub(s1, mjs3);
    float2 w1O1 = INV ? make_float2(C_SQ2 * (O1.x - O1.y), C_SQ2 * (O1.x + O1.y))
                      : make_float2(C_SQ2 * (O1.x + O1.y), C_SQ2 * (O1.y - O1.x));
    float2 w2O2 = INV ? make_float2(-O2.y, O2.x) : make_float2(O2.y, -O2.x);
    float2 w3O3 = INV ? make_float2(-C_SQ2 * (O3.x + O3.y), C_SQ2 * (O3.x - O3.y))
                      : make_float2(C_SQ2 * (O3.y - O3.x), -C_SQ2 * (O3.x + O3.y));
    float2 X[8];
    X[0] = cadd(E0, O0);   X[4] = csub(E0, O0);
    X[1] = cadd(E1, w1O1); X[5] = csub(E1, w1O1);
    X[2] = cadd(E2, w2O2); X[6] = csub(E2, w2O2);
    X[3] = cadd(E3, w3O3); X[7] = csub(E3, w3O3);
    int b8 = 8 * u + k;
    dst[PHY(b8)] = X[0];
#pragma unroll
    for (int j = 1; j < 8; ++j) {
        float2 w = g_tw[j * u];
        if (INV) w.y = -w.y;
        dst[PHY(b8 + j * m)] = cmul(w, X[j]);
    }
}

// generic radix-8 stage over smem
template <int NT, int INV>
__device__ __forceinline__ void r8_stage(const float2* src, float2* dst, int tid, int m) {
#pragma unroll
    for (int it = 0; it < 1024 / NT; ++it) {
        int bf = tid + it * NT;
        int k = bf & (m - 1);
        int u = bf - k;
        float2 x0 = src[PHY(bf)];
        float2 x1 = src[PHY(bf + 1024)];
        float2 x2 = src[PHY(bf + 2048)];
        float2 x3 = src[PHY(bf + 3072)];
        float2 x4 = src[PHY(bf + 4096)];
        float2 x5 = src[PHY(bf + 5120)];
        float2 x6 = src[PHY(bf + 6144)];
        float2 x7 = src[PHY(bf + 7168)];
        dft8_store<INV>(dst, u, k, m,
                        cadd(x0, x4), csub(x0, x4), cadd(x2, x6), csub(x2, x6),
                        cadd(x1, x5), csub(x1, x5), cadd(x3, x7), csub(x3, x7));
    }
    __syncthreads();
}

// fft_F: single CTA; computes g_tw itself, then FFT of f, then writes g_F.
__global__ __launch_bounds__(256) void fft_F_kernel() {
    extern __shared__ float2 sm[];
    float2* A = sm;
    float2* B = sm + FFT_BUF;
    int tid = threadIdx.x;
    // twiddle table (also used later by conv)
#pragma unroll
    for (int it = 0; it < 32; ++it) {
        int n = tid + it * 256;
        float s, c;
        sincospif(-2.0f * (float)n / (float)FFT_N, &s, &c);
        g_tw[n] = make_float2(c, s);
    }
    // input
#pragma unroll
    for (int it = 0; it < 32; ++it) {
        int d = tid + it * 256;
        float v = 0.f;
        if (d < L) {
            float base = (d == 0) ? EPSV : ((float)d * DTF + EPSV);
            v = powf(base, HEXP);
        }
        A[PHY(d)] = make_float2(v, 0.f);
    }
    __syncthreads();
    {
        float2* src = A;
        float2* dst = B;
        int m = 1;
#pragma unroll 1
        for (int s = 0; s < 4; ++s) {
            r8_stage<256, 0>(src, dst, tid, m);
            float2* t = src; src = dst; dst = t;
            m <<= 3;
        }
        const float scale = 1.0f / (float)FFT_N;
#pragma unroll
        for (int it = 0; it < 16; ++it) {
            int k = tid + it * 256;
            float2 a = src[PHY(k)];
            float2 b = src[PHY(k + FFT_N / 2)];
            float2 lo = cadd(a, b);
            float2 hi = csub(a, b);
            g_F[k] = make_float2(lo.x * scale, lo.y * scale);
            g_F[k + FFT_N / 2] = make_float2(hi.x * scale, hi.y * scale);
        }
    }
}

// ---------------- conv: fused, zero-pad-aware, half-output, NT=512 -----------
#define CONV_NT 512
__global__ __launch_bounds__(CONV_NT) void conv_kernel() {
    extern __shared__ float2 sm[];
    float2* A = sm;
    float2* B = sm + FFT_BUF;
    int tid = threadIdx.x;
    int c2 = blockIdx.x * 2;
    const float* __restrict__ ya = g_Yt + (size_t)c2 * L;
    const float* __restrict__ yb = g_Yt + (size_t)(c2 + 1) * L;

    // ---- forward stage 0 (m=1) straight from global; x4..x7 = 0 ----
#pragma unroll
    for (int it = 0; it < 1024 / CONV_NT; ++it) {
        int bf = tid + it * CONV_NT;
        float2 x0 = make_float2(ya[bf], yb[bf]);
        float2 x1 = make_float2(ya[bf + 1024], yb[bf + 1024]);
        float2 x2 = make_float2(ya[bf + 2048], yb[bf + 2048]);
        float2 x3 = make_float2(ya[bf + 3072], yb[bf + 3072]);
        // x4..7 = 0  =>  t0=t1=x0, t2=t3=x2, s0=s1=x1, s2=s3=x3
        dft8_store<0>(A, bf, 0, 1, x0, x0, x2, x2, x1, x1, x3, x3);
    }
    __syncthreads();
    // ---- forward stages 1..3 ----
    r8_stage<CONV_NT, 0>(A, B, tid, 8);
    r8_stage<CONV_NT, 0>(B, A, tid, 64);
    r8_stage<CONV_NT, 0>(A, B, tid, 512);
    // ---- forward final r2 fused with F multiply -> A ----
#pragma unroll
    for (int it = 0; it < 4096 / CONV_NT; ++it) {
        int k = tid + it * CONV_NT;
        float2 a = B[PHY(k)];
        float2 b = B[PHY(k + FFT_N / 2)];
        A[PHY(k)] = cmul(cadd(a, b), g_F[k]);
        A[PHY(k + FFT_N / 2)] = cmul(csub(a, b), g_F[k + FFT_N / 2]);
    }
    __syncthreads();
    // ---- inverse stages 0..3 ----
    r8_stage<CONV_NT, 1>(A, B, tid, 1);
    r8_stage<CONV_NT, 1>(B, A, tid, 8);
    r8_stage<CONV_NT, 1>(A, B, tid, 64);
    r8_stage<CONV_NT, 1>(B, A, tid, 512);
    // ---- inverse final r2: only outputs k < 4096 needed; write coalesced ----
    float* __restrict__ oa = g_outT + (size_t)c2 * L;
    float* __restrict__ ob = g_outT + (size_t)(c2 + 1) * L;
#pragma unroll
    for (int it = 0; it < 4096 / CONV_NT; ++it) {
        int k = tid + it * CONV_NT;
        float2 a = A[PHY(k)];
        float2 b = A[PHY(k + FFT_N / 2)];
        float2 s = cadd(a, b);
        oa[k] = s.x;
        ob[k] = s.y;
    }
}

// g_outT [c][i] -> out [i][c]; 64x64 tile, float2 both directions
__global__ void transpose_out_kernel(float* __restrict__ out) {
    __shared__ float2 t2[64][33];
    int i0 = blockIdx.x * 64, c0 = blockIdx.y * 64;
    int tx = threadIdx.x, ty = threadIdx.y;  // (32, 8)
#pragma unroll
    for (int k = 0; k < 8; ++k) {
        int r = ty + 8 * k;
        t2[r][tx] = *reinterpret_cast<const float2*>(&g_outT[(size_t)(c0 + r) * L + i0 + 2 * tx]);
    }
    __syncthreads();
#pragma unroll
    for (int k = 0; k < 8; ++k) {
        int r = ty + 8 * k;
        float2 p0 = t2[2 * tx][r >> 1];
        float2 p1 = t2[2 * tx + 1][r >> 1];
        float2 o;
        o.x = (r & 1) ? p0.y : p0.x;
        o.y = (r & 1) ? p1.y : p1.x;
        *reinterpret_cast<float2*>(&out[(size_t)(i0 + r) * DV + c0 + 2 * tx]) = o;
    }
}

// ---------------- GEMM1 compute core: warp tile 64x64 -----------------------
__device__ __forceinline__ void compute_stage64(uint32_t sbase, int lane, int wm, int wn,
                                                float acc[4][8][4]) {
    const int arow = lane & 15;
    const int acolb = (lane >> 4) << 4;
    const int brow = (lane & 7) + ((lane >> 4) << 3);
    const int bcolb = ((lane >> 3) & 1) << 4;
#pragma unroll
    for (int kk = 0; kk < 2; ++kk) {
        uint32_t aH[4][4], aL[4][4];
#pragma unroll
        for (int mi = 0; mi < 4; ++mi) {
            uint32_t o = SW64((uint32_t)((wm * 64 + mi * 16 + arow) * 64 + acolb)) ^ (kk << 5);
            ldsm4(aH[mi], sbase + T_AHI + o);
            ldsm4(aL[mi], sbase + T_ALO + o);
        }
#pragma unroll
        for (int pi = 0; pi < 4; ++pi) {
            uint32_t bH[4], bL[4];
            uint32_t o = SW64((uint32_t)((wn * 64 + pi * 16 + brow) * 64 + bcolb)) ^ (kk << 5);
            ldsm4(bH, sbase + T_BHI + o);
            ldsm4(bL, sbase + T_BLO + o);
#pragma unroll
            for (int mi = 0; mi < 4; ++mi)
#pragma unroll
                for (int q = 0; q < 2; ++q) {
                    mma_bf16(acc[mi][pi * 2 + q], aH[mi], &bH[q * 2]);
                    mma_bf16(acc[mi][pi * 2 + q], aH[mi], &bL[q * 2]);
                    mma_bf16(acc[mi][pi * 2 + q], aL[mi], &bH[q * 2]);
                }
        }
    }
}

__global__ __launch_bounds__(128, 2) void gemm1_mma() {
    extern __shared__ char smem[];
    const uint32_t sb = smem_u32(smem);
    const int tid = threadIdx.x, lane = tid & 31, wid = tid >> 5;
    const int wm = wid & 1, wn = (wid >> 1) & 1;
    const int l0 = blockIdx.x * 128;
    const int v0 = blockIdx.y * 128;
    const int KT = DE / 32;

    float acc[4][8][4];
#pragma unroll
    for (int mi = 0; mi < 4; ++mi)
#pragma unroll
        for (int ni = 0; ni < 8; ++ni)
#pragma unroll
            for (int r = 0; r < 4; ++r) acc[mi][ni][r] = 0.f;

#pragma unroll
    for (int s = 0; s < 2; ++s) {
        uint32_t st = sb + s * STAGE_BYTES;
        int k0 = s * 32;
        fill_tile32(st + T_AHI, g_W_hi, v0, k0, DE, tid);
        fill_tile32(st + T_ALO, g_W_lo, v0, k0, DE, tid);
        fill_tile32(st + T_BHI, g_Et_hi, l0, k0, DE, tid);
        fill_tile32(st + T_BLO, g_Et_lo, l0, k0, DE, tid);
        CP_COMMIT();
    }
    for (int kt = 0; kt < KT; ++kt) {
        int ls = kt + 2;
        if (ls < KT) {
            uint32_t st = sb + (ls % 3) * STAGE_BYTES;
            int k0 = ls * 32;
            fill_tile32(st + T_AHI, g_W_hi, v0, k0, DE, tid);
            fill_tile32(st + T_ALO, g_W_lo, v0, k0, DE, tid);
            fill_tile32(st + T_BHI, g_Et_hi, l0, k0, DE, tid);
            fill_tile32(st + T_BLO, g_Et_lo, l0, k0, DE, tid);
        }
        CP_COMMIT();
        CP_WAIT2();
        __syncthreads();
        compute_stage64(sb + (kt % 3) * STAGE_BYTES, lane, wm, wn, acc);
        __syncthreads();
    }

#pragma unroll
    for (int mi = 0; mi < 4; ++mi)
#pragma unroll
        for (int ni = 0; ni < 8; ++ni) {
            const float* c = acc[mi][ni];
            int v_ = v0 + wm * 64 + mi * 16 + (lane >> 2);
            int l_ = l0 + wn * 64 + ni * 8 + 2 * (lane & 3);
#pragma unroll
            for (int h = 0; h < 2; ++h) {
                float2 p;
                p.x = c[2 * h];
                p.y = c[2 * h + 1];
                *reinterpret_cast<float2*>(&g_Yt[(size_t)(v_ + 8 * h) * L + l_]) = p;
            }
        }
}

// ---------------------------------------------------------------------------
#define FFT_SMEM (2 * FFT_BUF * (int)sizeof(float2))

extern "C" void kernel_launch(void* const* d_in, const int* in_sizes, int n_in,
                              void* d_out, int out_size) {
    const float* E = (const float*)d_in[0];   // (1024, 4096)
    const float* W = (const float*)d_in[1];   // (1024, 1024)
    float* out = (float*)d_out;               // (4096, 1024)

    cudaFuncSetAttribute(gemm1_mma, cudaFuncAttributeMaxDynamicSharedMemorySize, GEMM_SMEM);
    cudaFuncSetAttribute(fft_F_kernel, cudaFuncAttributeMaxDynamicSharedMemorySize, FFT_SMEM);
    cudaFuncSetAttribute(conv_kernel, cudaFuncAttributeMaxDynamicSharedMemorySize, FFT_SMEM);

    fft_F_kernel<<<1, 256, FFT_SMEM>>>();
    transpose_E_kernel<<<dim3(L / 32, DE / 64), dim3(32, 8)>>>(E);
    convert_W_kernel<<<(DV * DE) / (256 * 8), 256>>>(W);
    gemm1_mma<<<dim3(L / 128, DV / 128), 128, GEMM_SMEM>>>();
    conv_kernel<<<DV / 2, CONV_NT, FFT_SMEM>>>();
    transpose_out_kernel<<<dim3(L / 64, DV / 64), dim3(32, 8)>>>(out);
}

// round 13
// speedup vs baseline: 1.2265x; 1.1711x over previous
#include <cuda_runtime.h>
#include <cuda_fp16.h>
#include <cstdint>

#define L 4096
#define DE 1024
#define DV 1024
#define HEXP 0.2f
#define DTF (1.0f / 4096.0f)
#define EPSV 1e-8f
#define FFT_N 8192

// ---------------- device scratch (static, no runtime alloc) ----------------
__device__ __half g_Et_hi[L * DE];          // E^T hi fp16 ([l][e])
__device__ __half g_Et_lo[L * DE];          // E^T lo fp16
__device__ __half g_W_h[DV * DE];           // W single fp16 ([v][e])
__device__ float g_Yt[(size_t)DV * L];      // Y^T fp32 ([v][l], l contiguous)
__device__ float g_outT[(size_t)DV * L];    // conv result [c][i]
__device__ float2 g_tw[FFT_N];              // exp(-2*pi*i*n/N)
__device__ float2 g_F[FFT_N];               // FFT(f_padded)/N

// ---------------- helpers ---------------------------------------------------
__device__ __forceinline__ uint32_t smem_u32(const void* p) {
    uint32_t a;
    asm("{ .reg .u64 t; cvta.to.shared.u64 t, %1; cvt.u32.u64 %0, t; }" : "=r"(a) : "l"(p));
    return a;
}
#define SW64(o) ((uint32_t)(o) ^ ((((uint32_t)(o)) >> 3) & 0x30u))

__device__ __forceinline__ void cpasync16(uint32_t dst, const void* src) {
    asm volatile("cp.async.cg.shared.global [%0], [%1], 16;" :: "r"(dst), "l"(src));
}
#define CP_COMMIT() asm volatile("cp.async.commit_group;" ::: "memory")
#define CP_WAIT2()  asm volatile("cp.async.wait_group 2;" ::: "memory")

__device__ __forceinline__ void ldsm4(uint32_t* r, uint32_t addr) {
    asm volatile("ldmatrix.sync.aligned.m8n8.x4.shared.b16 {%0,%1,%2,%3}, [%4];"
                 : "=r"(r[0]), "=r"(r[1]), "=r"(r[2]), "=r"(r[3]) : "r"(addr));
}
__device__ __forceinline__ void mma_fp16(float* c, const uint32_t* a, const uint32_t* b) {
    asm volatile(
        "mma.sync.aligned.m16n8k16.row.col.f32.f16.f16.f32 "
        "{%0,%1,%2,%3}, {%4,%5,%6,%7}, {%8,%9}, {%0,%1,%2,%3};"
        : "+f"(c[0]), "+f"(c[1]), "+f"(c[2]), "+f"(c[3])
        : "r"(a[0]), "r"(a[1]), "r"(a[2]), "r"(a[3]), "r"(b[0]), "r"(b[1]));
}

__device__ __forceinline__ float2 cmul(float2 a, float2 b) {
    return make_float2(a.x * b.x - a.y * b.y, a.x * b.y + a.y * b.x);
}
__device__ __forceinline__ float2 cadd(float2 a, float2 b) { return make_float2(a.x + b.x, a.y + b.y); }
__device__ __forceinline__ float2 csub(float2 a, float2 b) { return make_float2(a.x - b.x, a.y - b.y); }

// ---------------- GEMM tiling: CTA 128x128, 4 warps (64x64 each), BK=32 -----
// Per stage: W(8K) EtHi(8K) EtLo(8K) = 24KB.  3 stages = 72KB.
#define STAGE_BYTES 24576
#define T_A   0
#define T_BHI 8192
#define T_BLO 16384
#define GEMM_SMEM (3 * STAGE_BYTES)

__device__ __forceinline__ void fill_tile32(uint32_t dstbase,
                                            const __half* __restrict__ g,
                                            int row0, int k0, int stride, int tid) {
#pragma unroll
    for (int i = 0; i < 4; ++i) {
        int q = tid + i * 128;
        int r = q >> 2, c = q & 3;
        uint32_t o = (uint32_t)(r * 64 + c * 16);
        cpasync16(dstbase + SW64(o), g + (size_t)(row0 + r) * stride + k0 + c * 8);
    }
}

// ---------------- pre-kernels -----------------------------------------------
__global__ void transpose_E_kernel(const float* __restrict__ E) {
    __shared__ float t[64][33];
    int bx = blockIdx.x, by = blockIdx.y;
    int tx = threadIdx.x, ty = threadIdx.y;        // block (32, 8)
#pragma unroll
    for (int i = 0; i < 8; ++i)
        t[ty + 8 * i][tx] = E[(size_t)(by * 64 + ty + 8 * i) * L + bx * 32 + tx];
    __syncthreads();
#pragma unroll
    for (int i = 0; i < 4; ++i) {
        int ll = ty + 8 * i;
        float v0 = t[2 * tx][ll];
        float v1 = t[2 * tx + 1][ll];
        __half h0 = __float2half(v0);
        __half h1 = __float2half(v1);
        __half2 hp = __halves2half2(h0, h1);
        __half2 lp = __halves2half2(__float2half(v0 - __half2float(h0)),
                                    __float2half(v1 - __half2float(h1)));
        size_t o = (size_t)(bx * 32 + ll) * DE + by * 64 + 2 * tx;
        *reinterpret_cast<__half2*>(&g_Et_hi[o]) = hp;
        *reinterpret_cast<__half2*>(&g_Et_lo[o]) = lp;
    }
}

// W -> single fp16; float4 loads, 8 elems/thread, uint4 store
__global__ void convert_W_kernel(const float* __restrict__ W) {
    int base = (blockIdx.x * 256 + threadIdx.x) * 8;
    uint32_t pk[4];
#pragma unroll
    for (int h = 0; h < 2; ++h) {
        float4 v = *reinterpret_cast<const float4*>(&W[base + 4 * h]);
        __half2 p0 = __halves2half2(__float2half(v.x), __float2half(v.y));
        __half2 p1 = __halves2half2(__float2half(v.z), __float2half(v.w));
        pk[2 * h]     = *reinterpret_cast<uint32_t*>(&p0);
        pk[2 * h + 1] = *reinterpret_cast<uint32_t*>(&p1);
    }
    *reinterpret_cast<uint4*>(&g_W_h[base]) = make_uint4(pk[0], pk[1], pk[2], pk[3]);
}

// ---------------- radix-8 FFT machinery, skewed smem -------------------------
#define PHY(i) ((i) + ((i) >> 4))
#define FFT_BUF 8704
#define C_SQ2 0.70710678118654752f

template <int INV>
__device__ __forceinline__ void dft8_store(float2* dst, int u, int k, int m,
                                           float2 t0, float2 t1, float2 t2, float2 t3,
                                           float2 s0, float2 s1, float2 s2, float2 s3) {
    float2 mjt3 = INV ? make_float2(-t3.y, t3.x) : make_float2(t3.y, -t3.x);
    float2 mjs3 = INV ? make_float2(-s3.y, s3.x) : make_float2(s3.y, -s3.x);
    float2 E0 = cadd(t0, t2), E2 = csub(t0, t2);
    float2 E1 = cadd(t1, mjt3), E3 = csub(t1, mjt3);
    float2 O0 = cadd(s0, s2), O2 = csub(s0, s2);
    float2 O1 = cadd(s1, mjs3), O3 = csub(s1, mjs3);
    float2 w1O1 = INV ? make_float2(C_SQ2 * (O1.x - O1.y), C_SQ2 * (O1.x + O1.y))
                      : make_float2(C_SQ2 * (O1.x + O1.y), C_SQ2 * (O1.y - O1.x));
    float2 w2O2 = INV ? make_float2(-O2.y, O2.x) : make_float2(O2.y, -O2.x);
    float2 w3O3 = INV ? make_float2(-C_SQ2 * (O3.x + O3.y), C_SQ2 * (O3.x - O3.y))
                      : make_float2(C_SQ2 * (O3.y - O3.x), -C_SQ2 * (O3.x + O3.y));
    float2 X[8];
    X[0] = cadd(E0, O0);   X[4] = csub(E0, O0);
    X[1] = cadd(E1, w1O1); X[5] = csub(E1, w1O1);
    X[2] = cadd(E2, w2O2); X[6] = csub(E2, w2O2);
    X[3] = cadd(E3, w3O3); X[7] = csub(E3, w3O3);
    int b8 = 8 * u + k;
    dst[PHY(b8)] = X[0];
#pragma unroll
    for (int j = 1; j < 8; ++j) {
        float2 w = g_tw[j * u];
        if (INV) w.y = -w.y;
        dst[PHY(b8 + j * m)] = cmul(w, X[j]);
    }
}

template <int NT, int INV>
__device__ __forceinline__ void r8_stage(const float2* src, float2* dst, int tid, int m) {
#pragma unroll
    for (int it = 0; it < 1024 / NT; ++it) {
        int bf = tid + it * NT;
        int k = bf & (m - 1);
        int u = bf - k;
        float2 x0 = src[PHY(bf)];
        float2 x1 = src[PHY(bf + 1024)];
        float2 x2 = src[PHY(bf + 2048)];
        float2 x3 = src[PHY(bf + 3072)];
        float2 x4 = src[PHY(bf + 4096)];
        float2 x5 = src[PHY(bf + 5120)];
        float2 x6 = src[PHY(bf + 6144)];
        float2 x7 = src[PHY(bf + 7168)];
        dft8_store<INV>(dst, u, k, m,
                        cadd(x0, x4), csub(x0, x4), cadd(x2, x6), csub(x2, x6),
                        cadd(x1, x5), csub(x1, x5), cadd(x3, x7), csub(x3, x7));
    }
    __syncthreads();
}

// fft_F: single CTA; computes g_tw, FFT of f, writes g_F.
__global__ __launch_bounds__(256) void fft_F_kernel() {
    extern __shared__ float2 sm[];
    float2* A = sm;
    float2* B = sm + FFT_BUF;
    int tid = threadIdx.x;
#pragma unroll
    for (int it = 0; it < 32; ++it) {
        int n = tid + it * 256;
        float s, c;
        sincospif(-2.0f * (float)n / (float)FFT_N, &s, &c);
        g_tw[n] = make_float2(c, s);
    }
#pragma unroll
    for (int it = 0; it < 32; ++it) {
        int d = tid + it * 256;
        float v = 0.f;
        if (d < L) {
            float base = (d == 0) ? EPSV : ((float)d * DTF + EPSV);
            v = powf(base, HEXP);
        }
        A[PHY(d)] = make_float2(v, 0.f);
    }
    __syncthreads();
    {
        float2* src = A;
        float2* dst = B;
        int m = 1;
#pragma unroll 1
        for (int s = 0; s < 4; ++s) {
            r8_stage<256, 0>(src, dst, tid, m);
            float2* t = src; src = dst; dst = t;
            m <<= 3;
        }
        const float scale = 1.0f / (float)FFT_N;
#pragma unroll
        for (int it = 0; it < 16; ++it) {
            int k = tid + it * 256;
            float2 a = src[PHY(k)];
            float2 b = src[PHY(k + FFT_N / 2)];
            float2 lo = cadd(a, b);
            float2 hi = csub(a, b);
            g_F[k] = make_float2(lo.x * scale, lo.y * scale);
            g_F[k + FFT_N / 2] = make_float2(hi.x * scale, hi.y * scale);
        }
    }
}

// ---------------- conv: fused, zero-pad-aware, half-output, NT=512 -----------
#define CONV_NT 512
__global__ __launch_bounds__(CONV_NT) void conv_kernel() {
    extern __shared__ float2 sm[];
    float2* A = sm;
    float2* B = sm + FFT_BUF;
    int tid = threadIdx.x;
    int c2 = blockIdx.x * 2;
    const float* __restrict__ ya = g_Yt + (size_t)c2 * L;
    const float* __restrict__ yb = g_Yt + (size_t)(c2 + 1) * L;

#pragma unroll
    for (int it = 0; it < 1024 / CONV_NT; ++it) {
        int bf = tid + it * CONV_NT;
        float2 x0 = make_float2(ya[bf], yb[bf]);
        float2 x1 = make_float2(ya[bf + 1024], yb[bf + 1024]);
        float2 x2 = make_float2(ya[bf + 2048], yb[bf + 2048]);
        float2 x3 = make_float2(ya[bf + 3072], yb[bf + 3072]);
        dft8_store<0>(A, bf, 0, 1, x0, x0, x2, x2, x1, x1, x3, x3);
    }
    __syncthreads();
    r8_stage<CONV_NT, 0>(A, B, tid, 8);
    r8_stage<CONV_NT, 0>(B, A, tid, 64);
    r8_stage<CONV_NT, 0>(A, B, tid, 512);
#pragma unroll
    for (int it = 0; it < 4096 / CONV_NT; ++it) {
        int k = tid + it * CONV_NT;
        float2 a = B[PHY(k)];
        float2 b = B[PHY(k + FFT_N / 2)];
        A[PHY(k)] = cmul(cadd(a, b), g_F[k]);
        A[PHY(k + FFT_N / 2)] = cmul(csub(a, b), g_F[k + FFT_N / 2]);
    }
    __syncthreads();
    r8_stage<CONV_NT, 1>(A, B, tid, 1);
    r8_stage<CONV_NT, 1>(B, A, tid, 8);
    r8_stage<CONV_NT, 1>(A, B, tid, 64);
    r8_stage<CONV_NT, 1>(B, A, tid, 512);
    float* __restrict__ oa = g_outT + (size_t)c2 * L;
    float* __restrict__ ob = g_outT + (size_t)(c2 + 1) * L;
#pragma unroll
    for (int it = 0; it < 4096 / CONV_NT; ++it) {
        int k = tid + it * CONV_NT;
        float2 a = A[PHY(k)];
        float2 b = A[PHY(k + FFT_N / 2)];
        float2 s = cadd(a, b);
        oa[k] = s.x;
        ob[k] = s.y;
    }
}

// g_outT [c][i] -> out [i][c]; 64x64 tile, float2 both directions
__global__ void transpose_out_kernel(float* __restrict__ out) {
    __shared__ float2 t2[64][33];
    int i0 = blockIdx.x * 64, c0 = blockIdx.y * 64;
    int tx = threadIdx.x, ty = threadIdx.y;  // (32, 8)
#pragma unroll
    for (int k = 0; k < 8; ++k) {
        int r = ty + 8 * k;
        t2[r][tx] = *reinterpret_cast<const float2*>(&g_outT[(size_t)(c0 + r) * L + i0 + 2 * tx]);
    }
    __syncthreads();
#pragma unroll
    for (int k = 0; k < 8; ++k) {
        int r = ty + 8 * k;
        float2 p0 = t2[2 * tx][r >> 1];
        float2 p1 = t2[2 * tx + 1][r >> 1];
        float2 o;
        o.x = (r & 1) ? p0.y : p0.x;
        o.y = (r & 1) ? p1.y : p1.x;
        *reinterpret_cast<float2*>(&out[(size_t)(i0 + r) * DV + c0 + 2 * tx]) = o;
    }
}

// ---------------- GEMM1 compute: fp16 2-term, warp tile 64x64 ----------------
__device__ __forceinline__ void compute_stage64(uint32_t sbase, int lane, int wm, int wn,
                                                float acc[4][8][4]) {
    const int arow = lane & 15;
    const int acolb = (lane >> 4) << 4;
    const int brow = (lane & 7) + ((lane >> 4) << 3);
    const int bcolb = ((lane >> 3) & 1) << 4;
#pragma unroll
    for (int kk = 0; kk < 2; ++kk) {
        uint32_t aF[4][4];
#pragma unroll
        for (int mi = 0; mi < 4; ++mi) {
            uint32_t o = SW64((uint32_t)((wm * 64 + mi * 16 + arow) * 64 + acolb)) ^ (kk << 5);
            ldsm4(aF[mi], sbase + T_A + o);
        }
#pragma unroll
        for (int pi = 0; pi < 4; ++pi) {
            uint32_t bH[4], bL[4];
            uint32_t o = SW64((uint32_t)((wn * 64 + pi * 16 + brow) * 64 + bcolb)) ^ (kk << 5);
            ldsm4(bH, sbase + T_BHI + o);
            ldsm4(bL, sbase + T_BLO + o);
#pragma unroll
            for (int mi = 0; mi < 4; ++mi)
#pragma unroll
                for (int q = 0; q < 2; ++q) {
                    mma_fp16(acc[mi][pi * 2 + q], aF[mi], &bH[q * 2]);
                    mma_fp16(acc[mi][pi * 2 + q], aF[mi], &bL[q * 2]);
                }
        }
    }
}

// GEMM1: Yt[v][l] = sum_e W[v][e] * Et[l][e];  A = W (fp16), B = Et (hi+lo fp16)
__global__ __launch_bounds__(128, 2) void gemm1_mma() {
    extern __shared__ char smem[];
    const uint32_t sb = smem_u32(smem);
    const int tid = threadIdx.x, lane = tid & 31, wid = tid >> 5;
    const int wm = wid & 1, wn = (wid >> 1) & 1;
    const int l0 = blockIdx.x * 128;
    const int v0 = blockIdx.y * 128;
    const int KT = DE / 32;

    float acc[4][8][4];
#pragma unroll
    for (int mi = 0; mi < 4; ++mi)
#pragma unroll
        for (int ni = 0; ni < 8; ++ni)
#pragma unroll
            for (int r = 0; r < 4; ++r) acc[mi][ni][r] = 0.f;

#pragma unroll
    for (int s = 0; s < 2; ++s) {
        uint32_t st = sb + s * STAGE_BYTES;
        int k0 = s * 32;
        fill_tile32(st + T_A,   g_W_h,   v0, k0, DE, tid);
        fill_tile32(st + T_BHI, g_Et_hi, l0, k0, DE, tid);
        fill_tile32(st + T_BLO, g_Et_lo, l0, k0, DE, tid);
        CP_COMMIT();
    }
    for (int kt = 0; kt < KT; ++kt) {
        int ls = kt + 2;
        if (ls < KT) {
            uint32_t st = sb + (ls % 3) * STAGE_BYTES;
            int k0 = ls * 32;
            fill_tile32(st + T_A,   g_W_h,   v0, k0, DE, tid);
            fill_tile32(st + T_BHI, g_Et_hi, l0, k0, DE, tid);
            fill_tile32(st + T_BLO, g_Et_lo, l0, k0, DE, tid);
        }
        CP_COMMIT();
        CP_WAIT2();
        __syncthreads();
        compute_stage64(sb + (kt % 3) * STAGE_BYTES, lane, wm, wn, acc);
        __syncthreads();
    }

#pragma unroll
    for (int mi = 0; mi < 4; ++mi)
#pragma unroll
        for (int ni = 0; ni < 8; ++ni) {
            const float* c = acc[mi][ni];
            int v_ = v0 + wm * 64 + mi * 16 + (lane >> 2);
            int l_ = l0 + wn * 64 + ni * 8 + 2 * (lane & 3);
#pragma unroll
            for (int h = 0; h < 2; ++h) {
                float2 p;
                p.x = c[2 * h];
                p.y = c[2 * h + 1];
                *reinterpret_cast<float2*>(&g_Yt[(size_t)(v_ + 8 * h) * L + l_]) = p;
            }
        }
}

// ---------------------------------------------------------------------------
#define FFT_SMEM (2 * FFT_BUF * (int)sizeof(float2))

extern "C" void kernel_launch(void* const* d_in, const int* in_sizes, int n_in,
                              void* d_out, int out_size) {
    const float* E = (const float*)d_in[0];   // (1024, 4096)
    const float* W = (const float*)d_in[1];   // (1024, 1024)
    float* out = (float*)d_out;               // (4096, 1024)

    cudaFuncSetAttribute(gemm1_mma, cudaFuncAttributeMaxDynamicSharedMemorySize, GEMM_SMEM);
    cudaFuncSetAttribute(fft_F_kernel, cudaFuncAttributeMaxDynamicSharedMemorySize, FFT_SMEM);
    cudaFuncSetAttribute(conv_kernel, cudaFuncAttributeMaxDynamicSharedMemorySize, FFT_SMEM);

    fft_F_kernel<<<1, 256, FFT_SMEM>>>();
    transpose_E_kernel<<<dim3(L / 32, DE / 64), dim3(32, 8)>>>(E);
    convert_W_kernel<<<(DV * DE) / (256 * 8), 256>>>(W);
    gemm1_mma<<<dim3(L / 128, DV / 128), 128, GEMM_SMEM>>>();
    conv_kernel<<<DV / 2, CONV_NT, FFT_SMEM>>>();
    transpose_out_kernel<<<dim3(L / 64, DV / 64), dim3(32, 8)>>>(out);
}

// round 14
// speedup vs baseline: 1.5188x; 1.2383x over previous
#include <cuda_runtime.h>
#include <cuda_fp16.h>
#include <cstdint>

#define L 4096
#define DE 1024
#define DV 1024
#define HEXP 0.2f
#define DTF (1.0f / 4096.0f)
#define EPSV 1e-8f
#define FFT_N 8192

// ---------------- device scratch (static, no runtime alloc) ----------------
__device__ __half g_Et_h[L * DE];           // E^T fp16 ([l][e])
__device__ __half g_W_h[DV * DE];           // W fp16 ([v][e])
__device__ float g_Yt[(size_t)DV * L];      // Y^T fp32 ([v][l], l contiguous)
__device__ float g_outT[(size_t)DV * L];    // conv result [c][i]
__device__ float2 g_tw[FFT_N];              // exp(-2*pi*i*n/N)
__device__ float2 g_F[FFT_N];               // FFT(f_padded)/N

// ---------------- helpers ---------------------------------------------------
__device__ __forceinline__ uint32_t smem_u32(const void* p) {
    uint32_t a;
    asm("{ .reg .u64 t; cvta.to.shared.u64 t, %1; cvt.u32.u64 %0, t; }" : "=r"(a) : "l"(p));
    return a;
}
#define SW64(o) ((uint32_t)(o) ^ ((((uint32_t)(o)) >> 3) & 0x30u))

__device__ __forceinline__ void cpasync16(uint32_t dst, const void* src) {
    asm volatile("cp.async.cg.shared.global [%0], [%1], 16;" :: "r"(dst), "l"(src));
}
#define CP_COMMIT() asm volatile("cp.async.commit_group;" ::: "memory")
#define CP_WAIT2()  asm volatile("cp.async.wait_group 2;" ::: "memory")

__device__ __forceinline__ void ldsm4(uint32_t* r, uint32_t addr) {
    asm volatile("ldmatrix.sync.aligned.m8n8.x4.shared.b16 {%0,%1,%2,%3}, [%4];"
                 : "=r"(r[0]), "=r"(r[1]), "=r"(r[2]), "=r"(r[3]) : "r"(addr));
}
__device__ __forceinline__ void mma_fp16(float* c, const uint32_t* a, const uint32_t* b) {
    asm volatile(
        "mma.sync.aligned.m16n8k16.row.col.f32.f16.f16.f32 "
        "{%0,%1,%2,%3}, {%4,%5,%6,%7}, {%8,%9}, {%0,%1,%2,%3};"
        : "+f"(c[0]), "+f"(c[1]), "+f"(c[2]), "+f"(c[3])
        : "r"(a[0]), "r"(a[1]), "r"(a[2]), "r"(a[3]), "r"(b[0]), "r"(b[1]));
}

__device__ __forceinline__ float2 cmul(float2 a, float2 b) {
    return make_float2(a.x * b.x - a.y * b.y, a.x * b.y + a.y * b.x);
}
__device__ __forceinline__ float2 cadd(float2 a, float2 b) { return make_float2(a.x + b.x, a.y + b.y); }
__device__ __forceinline__ float2 csub(float2 a, float2 b) { return make_float2(a.x - b.x, a.y - b.y); }

// ---------------- GEMM tiling: CTA 128x128, 4 warps (64x64 each), BK=32 -----
// Per stage: W(8K) Et(8K) = 16KB.  3 stages = 48KB.
#define STAGE_BYTES 16384
#define T_A 0
#define T_B 8192
#define GEMM_SMEM (3 * STAGE_BYTES)

__device__ __forceinline__ void fill_tile32(uint32_t dstbase,
                                            const __half* __restrict__ g,
                                            int row0, int k0, int stride, int tid) {
#pragma unroll
    for (int i = 0; i < 4; ++i) {
        int q = tid + i * 128;
        int r = q >> 2, c = q & 3;
        uint32_t o = (uint32_t)(r * 64 + c * 16);
        cpasync16(dstbase + SW64(o), g + (size_t)(row0 + r) * stride + k0 + c * 8);
    }
}

// ---------------- pre-kernels -----------------------------------------------
__global__ void transpose_E_kernel(const float* __restrict__ E) {
    __shared__ float t[64][33];
    int bx = blockIdx.x, by = blockIdx.y;
    int tx = threadIdx.x, ty = threadIdx.y;        // block (32, 8)
#pragma unroll
    for (int i = 0; i < 8; ++i)
        t[ty + 8 * i][tx] = E[(size_t)(by * 64 + ty + 8 * i) * L + bx * 32 + tx];
    __syncthreads();
#pragma unroll
    for (int i = 0; i < 4; ++i) {
        int ll = ty + 8 * i;
        float v0 = t[2 * tx][ll];
        float v1 = t[2 * tx + 1][ll];
        __half2 hp = __halves2half2(__float2half(v0), __float2half(v1));
        size_t o = (size_t)(bx * 32 + ll) * DE + by * 64 + 2 * tx;
        *reinterpret_cast<__half2*>(&g_Et_h[o]) = hp;
    }
}

// W -> fp16; float4 loads, 8 elems/thread, uint4 store
__global__ void convert_W_kernel(const float* __restrict__ W) {
    int base = (blockIdx.x * 256 + threadIdx.x) * 8;
    uint32_t pk[4];
#pragma unroll
    for (int h = 0; h < 2; ++h) {
        float4 v = *reinterpret_cast<const float4*>(&W[base + 4 * h]);
        __half2 p0 = __halves2half2(__float2half(v.x), __float2half(v.y));
        __half2 p1 = __halves2half2(__float2half(v.z), __float2half(v.w));
        pk[2 * h]     = *reinterpret_cast<uint32_t*>(&p0);
        pk[2 * h + 1] = *reinterpret_cast<uint32_t*>(&p1);
    }
    *reinterpret_cast<uint4*>(&g_W_h[base]) = make_uint4(pk[0], pk[1], pk[2], pk[3]);
}

// ---------------- radix-8 FFT machinery, skewed smem -------------------------
#define PHY(i) ((i) + ((i) >> 4))
#define FFT_BUF 8704
#define C_SQ2 0.70710678118654752f

template <int INV>
__device__ __forceinline__ void dft8_store(float2* dst, int u, int k, int m,
                                           float2 t0, float2 t1, float2 t2, float2 t3,
                                           float2 s0, float2 s1, float2 s2, float2 s3) {
    float2 mjt3 = INV ? make_float2(-t3.y, t3.x) : make_float2(t3.y, -t3.x);
    float2 mjs3 = INV ? make_float2(-s3.y, s3.x) : make_float2(s3.y, -s3.x);
    float2 E0 = cadd(t0, t2), E2 = csub(t0, t2);
    float2 E1 = cadd(t1, mjt3), E3 = csub(t1, mjt3);
    float2 O0 = cadd(s0, s2), O2 = csub(s0, s2);
    float2 O1 = cadd(s1, mjs3), O3 = csub(s1, mjs3);
    float2 w1O1 = INV ? make_float2(C_SQ2 * (O1.x - O1.y), C_SQ2 * (O1.x + O1.y))
                      : make_float2(C_SQ2 * (O1.x + O1.y), C_SQ2 * (O1.y - O1.x));
    float2 w2O2 = INV ? make_float2(-O2.y, O2.x) : make_float2(O2.y, -O2.x);
    float2 w3O3 = INV ? make_float2(-C_SQ2 * (O3.x + O3.y), C_SQ2 * (O3.x - O3.y))
                      : make_float2(C_SQ2 * (O3.y - O3.x), -C_SQ2 * (O3.x + O3.y));
    float2 X[8];
    X[0] = cadd(E0, O0);   X[4] = csub(E0, O0);
    X[1] = cadd(E1, w1O1); X[5] = csub(E1, w1O1);
    X[2] = cadd(E2, w2O2); X[6] = csub(E2, w2O2);
    X[3] = cadd(E3, w3O3); X[7] = csub(E3, w3O3);
    int b8 = 8 * u + k;
    dst[PHY(b8)] = X[0];
#pragma unroll
    for (int j = 1; j < 8; ++j) {
        float2 w = g_tw[j * u];
        if (INV) w.y = -w.y;
        dst[PHY(b8 + j * m)] = cmul(w, X[j]);
    }
}

template <int NT, int INV>
__device__ __forceinline__ void r8_stage(const float2* src, float2* dst, int tid, int m) {
#pragma unroll
    for (int it = 0; it < 1024 / NT; ++it) {
        int bf = tid + it * NT;
        int k = bf & (m - 1);
        int u = bf - k;
        float2 x0 = src[PHY(bf)];
        float2 x1 = src[PHY(bf + 1024)];
        float2 x2 = src[PHY(bf + 2048)];
        float2 x3 = src[PHY(bf + 3072)];
        float2 x4 = src[PHY(bf + 4096)];
        float2 x5 = src[PHY(bf + 5120)];
        float2 x6 = src[PHY(bf + 6144)];
        float2 x7 = src[PHY(bf + 7168)];
        dft8_store<INV>(dst, u, k, m,
                        cadd(x0, x4), csub(x0, x4), cadd(x2, x6), csub(x2, x6),
                        cadd(x1, x5), csub(x1, x5), cadd(x3, x7), csub(x3, x7));
    }
    __syncthreads();
}

// fft_F: single CTA; computes g_tw, FFT of f, writes g_F.
__global__ __launch_bounds__(256) void fft_F_kernel() {
    extern __shared__ float2 sm[];
    float2* A = sm;
    float2* B = sm + FFT_BUF;
    int tid = threadIdx.x;
#pragma unroll
    for (int it = 0; it < 32; ++it) {
        int n = tid + it * 256;
        float s, c;
        sincospif(-2.0f * (float)n / (float)FFT_N, &s, &c);
        g_tw[n] = make_float2(c, s);
    }
#pragma unroll
    for (int it = 0; it < 32; ++it) {
        int d = tid + it * 256;
        float v = 0.f;
        if (d < L) {
            float base = (d == 0) ? EPSV : ((float)d * DTF + EPSV);
            v = powf(base, HEXP);
        }
        A[PHY(d)] = make_float2(v, 0.f);
    }
    __syncthreads();
    {
        float2* src = A;
        float2* dst = B;
        int m = 1;
#pragma unroll 1
        for (int s = 0; s < 4; ++s) {
            r8_stage<256, 0>(src, dst, tid, m);
            float2* t = src; src = dst; dst = t;
            m <<= 3;
        }
        const float scale = 1.0f / (float)FFT_N;
#pragma unroll
        for (int it = 0; it < 16; ++it) {
            int k = tid + it * 256;
            float2 a = src[PHY(k)];
            float2 b = src[PHY(k + FFT_N / 2)];
            float2 lo = cadd(a, b);
            float2 hi = csub(a, b);
            g_F[k] = make_float2(lo.x * scale, lo.y * scale);
            g_F[k + FFT_N / 2] = make_float2(hi.x * scale, hi.y * scale);
        }
    }
}

// ---------------- conv: fused, zero-pad-aware, half-output, NT=512 -----------
#define CONV_NT 512
__global__ __launch_bounds__(CONV_NT) void conv_kernel() {
    extern __shared__ float2 sm[];
    float2* A = sm;
    float2* B = sm + FFT_BUF;
    int tid = threadIdx.x;
    int c2 = blockIdx.x * 2;
    const float* __restrict__ ya = g_Yt + (size_t)c2 * L;
    const float* __restrict__ yb = g_Yt + (size_t)(c2 + 1) * L;

#pragma unroll
    for (int it = 0; it < 1024 / CONV_NT; ++it) {
        int bf = tid + it * CONV_NT;
        float2 x0 = make_float2(ya[bf], yb[bf]);
        float2 x1 = make_float2(ya[bf + 1024], yb[bf + 1024]);
        float2 x2 = make_float2(ya[bf + 2048], yb[bf + 2048]);
        float2 x3 = make_float2(ya[bf + 3072], yb[bf + 3072]);
        dft8_store<0>(A, bf, 0, 1, x0, x0, x2, x2, x1, x1, x3, x3);
    }
    __syncthreads();
    r8_stage<CONV_NT, 0>(A, B, tid, 8);
    r8_stage<CONV_NT, 0>(B, A, tid, 64);
    r8_stage<CONV_NT, 0>(A, B, tid, 512);
#pragma unroll
    for (int it = 0; it < 4096 / CONV_NT; ++it) {
        int k = tid + it * CONV_NT;
        float2 a = B[PHY(k)];
        float2 b = B[PHY(k + FFT_N / 2)];
        A[PHY(k)] = cmul(cadd(a, b), g_F[k]);
        A[PHY(k + FFT_N / 2)] = cmul(csub(a, b), g_F[k + FFT_N / 2]);
    }
    __syncthreads();
    r8_stage<CONV_NT, 1>(A, B, tid, 1);
    r8_stage<CONV_NT, 1>(B, A, tid, 8);
    r8_stage<CONV_NT, 1>(A, B, tid, 64);
    r8_stage<CONV_NT, 1>(B, A, tid, 512);
    float* __restrict__ oa = g_outT + (size_t)c2 * L;
    float* __restrict__ ob = g_outT + (size_t)(c2 + 1) * L;
#pragma unroll
    for (int it = 0; it < 4096 / CONV_NT; ++it) {
        int k = tid + it * CONV_NT;
        float2 a = A[PHY(k)];
        float2 b = A[PHY(k + FFT_N / 2)];
        float2 s = cadd(a, b);
        oa[k] = s.x;
        ob[k] = s.y;
    }
}

// g_outT [c][i] -> out [i][c]; 64x64 tile, float2 both directions
__global__ void transpose_out_kernel(float* __restrict__ out) {
    __shared__ float2 t2[64][33];
    int i0 = blockIdx.x * 64, c0 = blockIdx.y * 64;
    int tx = threadIdx.x, ty = threadIdx.y;  // (32, 8)
#pragma unroll
    for (int k = 0; k < 8; ++k) {
        int r = ty + 8 * k;
        t2[r][tx] = *reinterpret_cast<const float2*>(&g_outT[(size_t)(c0 + r) * L + i0 + 2 * tx]);
    }
    __syncthreads();
#pragma unroll
    for (int k = 0; k < 8; ++k) {
        int r = ty + 8 * k;
        float2 p0 = t2[2 * tx][r >> 1];
        float2 p1 = t2[2 * tx + 1][r >> 1];
        float2 o;
        o.x = (r & 1) ? p0.y : p0.x;
        o.y = (r & 1) ? p1.y : p1.x;
        *reinterpret_cast<float2*>(&out[(size_t)(i0 + r) * DV + c0 + 2 * tx]) = o;
    }
}

// ---------------- GEMM1 compute: single fp16, warp tile 64x64 ----------------
__device__ __forceinline__ void compute_stage64(uint32_t sbase, int lane, int wm, int wn,
                                                float acc[4][8][4]) {
    const int arow = lane & 15;
    const int acolb = (lane >> 4) << 4;
    const int brow = (lane & 7) + ((lane >> 4) << 3);
    const int bcolb = ((lane >> 3) & 1) << 4;
#pragma unroll
    for (int kk = 0; kk < 2; ++kk) {
        uint32_t aF[4][4];
#pragma unroll
        for (int mi = 0; mi < 4; ++mi) {
            uint32_t o = SW64((uint32_t)((wm * 64 + mi * 16 + arow) * 64 + acolb)) ^ (kk << 5);
            ldsm4(aF[mi], sbase + T_A + o);
        }
#pragma unroll
        for (int pi = 0; pi < 4; ++pi) {
            uint32_t bF[4];
            uint32_t o = SW64((uint32_t)((wn * 64 + pi * 16 + brow) * 64 + bcolb)) ^ (kk << 5);
            ldsm4(bF, sbase + T_B + o);
#pragma unroll
            for (int mi = 0; mi < 4; ++mi)
#pragma unroll
                for (int q = 0; q < 2; ++q)
                    mma_fp16(acc[mi][pi * 2 + q], aF[mi], &bF[q * 2]);
        }
    }
}

// GEMM1: Yt[v][l] = sum_e W[v][e] * Et[l][e];  A = W (fp16), B = Et (fp16)
__global__ __launch_bounds__(128, 2) void gemm1_mma() {
    extern __shared__ char smem[];
    const uint32_t sb = smem_u32(smem);
    const int tid = threadIdx.x, lane = tid & 31, wid = tid >> 5;
    const int wm = wid & 1, wn = (wid >> 1) & 1;
    const int l0 = blockIdx.x * 128;
    const int v0 = blockIdx.y * 128;
    const int KT = DE / 32;

    float acc[4][8][4];
#pragma unroll
    for (int mi = 0; mi < 4; ++mi)
#pragma unroll
        for (int ni = 0; ni < 8; ++ni)
#pragma unroll
            for (int r = 0; r < 4; ++r) acc[mi][ni][r] = 0.f;

#pragma unroll
    for (int s = 0; s < 2; ++s) {
        uint32_t st = sb + s * STAGE_BYTES;
        int k0 = s * 32;
        fill_tile32(st + T_A, g_W_h,  v0, k0, DE, tid);
        fill_tile32(st + T_B, g_Et_h, l0, k0, DE, tid);
        CP_COMMIT();
    }
    for (int kt = 0; kt < KT; ++kt) {
        int ls = kt + 2;
        if (ls < KT) {
            uint32_t st = sb + (ls % 3) * STAGE_BYTES;
            int k0 = ls * 32;
            fill_tile32(st + T_A, g_W_h,  v0, k0, DE, tid);
            fill_tile32(st + T_B, g_Et_h, l0, k0, DE, tid);
        }
        CP_COMMIT();
        CP_WAIT2();
        __syncthreads();
        compute_stage64(sb + (kt % 3) * STAGE_BYTES, lane, wm, wn, acc);
        __syncthreads();
    }

#pragma unroll
    for (int mi = 0; mi < 4; ++mi)
#pragma unroll
        for (int ni = 0; ni < 8; ++ni) {
            const float* c = acc[mi][ni];
            int v_ = v0 + wm * 64 + mi * 16 + (lane >> 2);
            int l_ = l0 + wn * 64 + ni * 8 + 2 * (lane & 3);
#pragma unroll
            for (int h = 0; h < 2; ++h) {
                float2 p;
                p.x = c[2 * h];
                p.y = c[2 * h + 1];
                *reinterpret_cast<float2*>(&g_Yt[(size_t)(v_ + 8 * h) * L + l_]) = p;
            }
        }
}

// ---------------------------------------------------------------------------
#define FFT_SMEM (2 * FFT_BUF * (int)sizeof(float2))

extern "C" void kernel_launch(void* const* d_in, const int* in_sizes, int n_in,
                              void* d_out, int out_size) {
    const float* E = (const float*)d_in[0];   // (1024, 4096)
    const float* W = (const float*)d_in[1];   // (1024, 1024)
    float* out = (float*)d_out;               // (4096, 1024)

    cudaFuncSetAttribute(gemm1_mma, cudaFuncAttributeMaxDynamicSharedMemorySize, GEMM_SMEM);
    cudaFuncSetAttribute(fft_F_kernel, cudaFuncAttributeMaxDynamicSharedMemorySize, FFT_SMEM);
    cudaFuncSetAttribute(conv_kernel, cudaFuncAttributeMaxDynamicSharedMemorySize, FFT_SMEM);

    fft_F_kernel<<<1, 256, FFT_SMEM>>>();
    transpose_E_kernel<<<dim3(L / 32, DE / 64), dim3(32, 8)>>>(E);
    convert_W_kernel<<<(DV * DE) / (256 * 8), 256>>>(W);
    gemm1_mma<<<dim3(L / 128, DV / 128), 128, GEMM_SMEM>>>();
    conv_kernel<<<DV / 2, CONV_NT, FFT_SMEM>>>();
    transpose_out_kernel<<<dim3(L / 64, DV / 64), dim3(32, 8)>>>(out);
}